// round 12
// baseline (speedup 1.0000x reference)
#include <cuda_runtime.h>
#include <math.h>

#define N_ 128
#define H_ 256
#define B_ 16

// -------- device scratch --------
__device__ float g_P[H_*H_];        // W1^T W1
__device__ float g_Q[H_*H_];        // W2 W2^T
__device__ float g_W1T[H_*N_];      // W1T[h*N+i] = W1[i*H+h]
__device__ float g_W2T[N_*H_];      // W2T[k*H+h] = W2[h*N+k]
__device__ float g_s[B_*H_];
__device__ float g_c[B_*H_];
__device__ float g_Avec[B_*N_];
__device__ float g_Cvec[B_*N_];
__device__ float g_vn[B_];
__device__ float g_A2[B_*H_*H_];    // A2 = P S Q per sample
__device__ float g_part[B_*10];     // nrm^2/2 tile partials (10 upper tiles)
__device__ unsigned int g_cnt[B_];  // last-block-done counters

#define FFMA2(d, a, b) \
    asm("fma.rn.f32x2 %0, %1, %2, %0;" : "+l"(d) : "l"(a), "l"(b))
#define DUP2(d, f) \
    asm("mov.b64 %0, {%1, %1};" : "=l"(d) : "f"(f))
#define UNPK2(lo, hi, d) \
    asm("mov.b64 {%0, %1}, %2;" : "=f"(lo), "=f"(hi) : "l"(d))

#define MICRO_STEP_F32X2(As_, Bs_)                                      \
    {   float4 ra = *(const float4*)&As_[k][ty*4];                      \
        ulonglong2 rbp = *(const ulonglong2*)&Bs_[k][tx*4];             \
        unsigned long long ad0, ad1, ad2, ad3;                          \
        DUP2(ad0, ra.x); DUP2(ad1, ra.y);                               \
        DUP2(ad2, ra.z); DUP2(ad3, ra.w);                               \
        FFMA2(accp[0][0], ad0, rbp.x); FFMA2(accp[0][1], ad0, rbp.y);   \
        FFMA2(accp[1][0], ad1, rbp.x); FFMA2(accp[1][1], ad1, rbp.y);   \
        FFMA2(accp[2][0], ad2, rbp.x); FFMA2(accp[2][1], ad2, rbp.y);   \
        FFMA2(accp[3][0], ad3, rbp.x); FFMA2(accp[3][1], ad3, rbp.y);   \
    }

#define UNPACK_ACC()                                                    \
    float acc[4][4];                                                    \
    _Pragma("unroll")                                                   \
    for (int i = 0; i < 4; i++){                                        \
        UNPK2(acc[i][0], acc[i][1], accp[i][0]);                        \
        UNPK2(acc[i][2], acc[i][3], accp[i][1]);                        \
    }

// ==================== kernel 0: transposes ====================
__global__ void __launch_bounds__(256) k_tr(const float* __restrict__ W1,
                                            const float* __restrict__ W2){
    __shared__ float ts[32][33];
    int bid = blockIdx.x;
    int tid = threadIdx.x;
    int r0 = tid >> 5, cc = tid & 31;
    if (bid < 32){
        int ti = bid >> 3, th = bid & 7;
        #pragma unroll
        for (int r = r0; r < 32; r += 8)
            ts[r][cc] = W1[(ti*32 + r)*H_ + th*32 + cc];
        __syncthreads();
        #pragma unroll
        for (int r = r0; r < 32; r += 8)
            g_W1T[(th*32 + r)*N_ + ti*32 + cc] = ts[cc][r];
    } else {
        int b2 = bid - 32;
        int th = b2 >> 2, tk = b2 & 3;
        #pragma unroll
        for (int r = r0; r < 32; r += 8)
            ts[r][cc] = W2[(th*32 + r)*N_ + tk*32 + cc];
        __syncthreads();
        #pragma unroll
        for (int r = r0; r < 32; r += 8)
            g_W2T[(tk*32 + r)*H_ + th*32 + cc] = ts[cc][r];
    }
}

// ==================== stage 1: fused P/Q GEMM + vectors ====================
__global__ void __launch_bounds__(256) k_stage1(
        const float* __restrict__ W1, const float* __restrict__ W2,
        const float* __restrict__ tptr, const float* __restrict__ state,
        const float* __restrict__ x0,  const float* __restrict__ x1,
        const float* __restrict__ b1){
    int bid = blockIdx.x;
    int tid = threadIdx.x;

    if (bid < 32){
        int z = bid >> 4, tile = bid & 15;
        int g0 = (tile >> 2)*64, h0 = (tile & 3)*64;
        __shared__ float As[16][68];
        __shared__ float Bs[16][68];
        int ty = tid >> 4, tx = tid & 15;
        unsigned long long accp[4][2] = {{0ull,0ull},{0ull,0ull},{0ull,0ull},{0ull,0ull}};

        for (int a0 = 0; a0 < N_; a0 += 16){
            if (z == 0){
                int a = tid >> 4, q4 = (tid & 15)*4;
                *(float4*)&As[a][q4] = *(const float4*)&W1[(a0+a)*H_ + g0 + q4];
                *(float4*)&Bs[a][q4] = *(const float4*)&W1[(a0+a)*H_ + h0 + q4];
            } else {
                int gg = tid >> 2, kq = (tid & 3)*4;
                float4 av = *(const float4*)&W2[(g0+gg)*N_ + a0 + kq];
                float4 bv = *(const float4*)&W2[(h0+gg)*N_ + a0 + kq];
                As[kq+0][gg] = av.x; As[kq+1][gg] = av.y;
                As[kq+2][gg] = av.z; As[kq+3][gg] = av.w;
                Bs[kq+0][gg] = bv.x; Bs[kq+1][gg] = bv.y;
                Bs[kq+2][gg] = bv.z; Bs[kq+3][gg] = bv.w;
            }
            __syncthreads();
            #pragma unroll
            for (int k = 0; k < 16; k++) MICRO_STEP_F32X2(As, Bs)
            __syncthreads();
        }
        UNPACK_ACC()
        float* dst = (z == 0) ? g_P : g_Q;
        #pragma unroll
        for (int i = 0; i < 4; i++){
            float4 o = make_float4(acc[i][0], acc[i][1], acc[i][2], acc[i][3]);
            *(float4*)&dst[(g0+ty*4+i)*H_ + h0 + tx*4] = o;
        }
        return;
    }

    // ---- per-sample vector pipeline: forced-MLP register batches ----
    int b = bid - 32;
    __shared__ float xs[N_], vs[N_], red[N_];
    __shared__ float swv[H_], cwy[H_], pvs[H_], cwz[H_];
    __shared__ float r1p[2][N_], r2p[2][N_], r1s[N_], r2s[N_];
    __shared__ float Ap[2][N_], Cp[2][N_];

    float tval = *tptr;
    float window = 4.f * tval * (1.f - tval);
    if (tid < N_){
        float dev = state[b*N_ + tid];
        float v   = state[(B_+b)*N_ + tid];
        float x0v = x0[b*N_ + tid];
        xs[tid] = x0v + tval*(x1[b*N_ + tid] - x0v) + window*dev;
        vs[tid] = v;
        red[tid] = v*v;
    }
    __syncthreads();

    if (tid < 32){
        float a0 = red[tid] + red[tid+32] + red[tid+64] + red[tid+96];
        #pragma unroll
        for (int o = 16; o; o >>= 1) a0 += __shfl_xor_sync(0xffffffffu, a0, o);
        if (tid == 0) g_vn[b] = sqrtf(a0);
    }

    int h = tid;
    float u = 0.f, y = 0.f, w = 0.f;
    for (int k0 = 0; k0 < N_; k0 += 16){
        float wb[16], tb[16];
        #pragma unroll
        for (int j = 0; j < 16; j++) wb[j] = W1[(k0+j)*H_ + h];
        #pragma unroll
        for (int j = 0; j < 16; j++) tb[j] = g_W2T[(k0+j)*H_ + h];
        #pragma unroll
        for (int j = 0; j < 16; j++){
            u += xs[k0+j]*wb[j];
            y += vs[k0+j]*wb[j];
            w += vs[k0+j]*tb[j];
        }
    }
    float th = tanhf(u + b1[h]);
    float s = 1.f - th*th;
    float c = -2.f*th*s;
    g_s[b*H_ + h] = s;
    g_c[b*H_ + h] = c;
    swv[h] = s*w;
    cwy[h] = c*w*y;
    __syncthreads();

    {
        int kk = tid & 127, half = tid >> 7;
        float s1 = 0.f, s2 = 0.f;
        for (int j0 = 0; j0 < 128; j0 += 16){
            float wb[16];
            #pragma unroll
            for (int j = 0; j < 16; j++) wb[j] = g_W1T[(half*128 + j0 + j)*N_ + kk];
            #pragma unroll
            for (int j = 0; j < 16; j++){
                s1 += wb[j]*swv[half*128 + j0 + j];
                s2 += wb[j]*cwy[half*128 + j0 + j];
            }
        }
        r1p[half][kk] = s1;
        r2p[half][kk] = s2;
    }
    __syncthreads();
    if (tid < N_){
        r1s[tid] = r1p[0][tid] + r1p[1][tid];
        r2s[tid] = r2p[0][tid] + r2p[1][tid];
    }
    __syncthreads();

    float z = 0.f, q2 = 0.f;
    for (int k0 = 0; k0 < N_; k0 += 16){
        float wb[16];
        #pragma unroll
        for (int j = 0; j < 16; j++) wb[j] = W1[(k0+j)*H_ + h];
        #pragma unroll
        for (int j = 0; j < 16; j++){
            z  += wb[j]*r1s[k0+j];
            q2 += wb[j]*r2s[k0+j];
        }
    }
    pvs[h] = c*y*z + s*q2;
    cwz[h] = c*w*z;
    __syncthreads();

    {
        int i = tid & 127, hf = tid >> 7;
        float A = 0.f, Cc = 0.f;
        for (int j0 = 0; j0 < 128; j0 += 16){
            float wa[16], wc[16];
            #pragma unroll
            for (int j = 0; j < 16; j++) wa[j] = W2[(hf*128 + j0 + j)*N_ + i];
            #pragma unroll
            for (int j = 0; j < 16; j++) wc[j] = g_W1T[(hf*128 + j0 + j)*N_ + i];
            #pragma unroll
            for (int j = 0; j < 16; j++){
                A  += wa[j]*pvs[hf*128 + j0 + j];
                Cc += wc[j]*cwz[hf*128 + j0 + j];
            }
        }
        Ap[hf][i] = A;
        Cp[hf][i] = Cc;
    }
    __syncthreads();
    if (tid < N_){
        g_Avec[b*N_ + tid] = Ap[0][tid] + Ap[1][tid];
        g_Cvec[b*N_ + tid] = 2.f*(Cp[0][tid] + Cp[1][tid]);
    }
}

// ==================== stage 2: A2[b] = P diag(s) Q (double-buffered) ====================
__global__ void __launch_bounds__(256) k_A2(){
    int b  = blockIdx.z;
    int g0 = blockIdx.y*64, h0 = blockIdx.x*64;
    int tid = threadIdx.x;
    if (blockIdx.x == 0 && blockIdx.y == 0 && tid == 0) g_cnt[b] = 0;
    int ty = tid >> 4, tx = tid & 15;
    __shared__ float Ps[2][16][68];
    __shared__ float Qs[2][16][68];
    __shared__ float ssm[H_];
    ssm[tid] = g_s[b*H_ + tid];
    unsigned long long accp[4][2] = {{0ull,0ull},{0ull,0ull},{0ull,0ull},{0ull,0ull}};

    int a = tid >> 4, q4 = (tid & 15)*4;
    float4 pv = *(const float4*)&g_P[a*H_ + g0 + q4];     // tile 0 (P symmetric)
    float4 qv = *(const float4*)&g_Q[a*H_ + h0 + q4];
    __syncthreads();                                      // ssm ready
    {
        float sa = ssm[a];
        *(float4*)&Ps[0][a][q4] = pv;
        qv.x *= sa; qv.y *= sa; qv.z *= sa; qv.w *= sa;
        *(float4*)&Qs[0][a][q4] = qv;
    }
    __syncthreads();

    for (int t = 0; t < 16; t++){
        int cur = t & 1;
        if (t < 15){
            pv = *(const float4*)&g_P[((t+1)*16 + a)*H_ + g0 + q4];
            qv = *(const float4*)&g_Q[((t+1)*16 + a)*H_ + h0 + q4];
        }
        #pragma unroll
        for (int k = 0; k < 16; k++) MICRO_STEP_F32X2(Ps[cur], Qs[cur])
        if (t < 15){
            float sa = ssm[(t+1)*16 + a];
            *(float4*)&Ps[cur^1][a][q4] = pv;
            qv.x *= sa; qv.y *= sa; qv.z *= sa; qv.w *= sa;
            *(float4*)&Qs[cur^1][a][q4] = qv;
        }
        __syncthreads();
    }
    UNPACK_ACC()
    float* dst = g_A2 + b*H_*H_;
    #pragma unroll
    for (int i = 0; i < 4; i++){
        float4 o = make_float4(acc[i][0], acc[i][1], acc[i][2], acc[i][3]);
        *(float4*)&dst[(g0+ty*4+i)*H_ + h0 + tx*4] = o;
    }
}

// ========== stage 3: M = P diag(s) A2^T (upper tiles only, symmetric summand) ==========
// f(g,h) = c_g c_h P_gh (Q_gh M_gh + A2_gh A2_hg) is symmetric in (g,h):
// compute 10 upper-triangular 64x64 tiles; off-diag tiles weight 2, diag per-element.
__global__ void __launch_bounds__(256) k_nrm(const float* __restrict__ state,
                                             float* __restrict__ out){
    const int gt_t[10] = {0,0,0,0,1,1,1,2,2,3};
    const int ht_t[10] = {0,1,2,3,1,2,3,2,3,3};
    int b  = blockIdx.z;
    int ti = blockIdx.x;
    int g0 = gt_t[ti]*64, h0 = ht_t[ti]*64;
    bool diag = (g0 == h0);
    int tid = threadIdx.x;
    int ty = tid >> 4, tx = tid & 15;
    __shared__ float As[2][16][68];
    __shared__ float Bs[2][16][68];
    __shared__ float Ts[64][65];       // mirror tile A2[h0.., g0..]
    __shared__ float ssm[H_];
    ssm[tid] = g_s[b*H_ + tid];
    unsigned long long accp[4][2] = {{0ull,0ull},{0ull,0ull},{0ull,0ull},{0ull,0ull}};

    const float* A2b = g_A2 + b*H_*H_;
    int a  = tid >> 4, q4 = (tid & 15)*4;
    int rw = tid >> 2, kq = (tid & 3)*4;

    #pragma unroll
    for (int p = 0; p < 4; p++){
        int f = tid + p*256;
        int row = f >> 4, c4 = (f & 15)*4;
        float4 tv = *(const float4*)&A2b[(h0+row)*H_ + g0 + c4];
        Ts[row][c4+0] = tv.x; Ts[row][c4+1] = tv.y;
        Ts[row][c4+2] = tv.z; Ts[row][c4+3] = tv.w;
    }

    float4 pv = *(const float4*)&g_P[a*H_ + g0 + q4];
    float4 bv = *(const float4*)&A2b[(h0+rw)*H_ + kq];
    __syncthreads();
    {
        float sa = ssm[a];
        pv.x *= sa; pv.y *= sa; pv.z *= sa; pv.w *= sa;
        *(float4*)&As[0][a][q4] = pv;
        Bs[0][kq+0][rw] = bv.x; Bs[0][kq+1][rw] = bv.y;
        Bs[0][kq+2][rw] = bv.z; Bs[0][kq+3][rw] = bv.w;
    }
    __syncthreads();

    for (int t = 0; t < 16; t++){
        int cur = t & 1;
        if (t < 15){
            pv = *(const float4*)&g_P[((t+1)*16 + a)*H_ + g0 + q4];
            bv = *(const float4*)&A2b[(h0+rw)*H_ + (t+1)*16 + kq];
        }
        #pragma unroll
        for (int k = 0; k < 16; k++) MICRO_STEP_F32X2(As[cur], Bs[cur])
        if (t < 15){
            float sa = ssm[(t+1)*16 + a];
            pv.x *= sa; pv.y *= sa; pv.z *= sa; pv.w *= sa;
            *(float4*)&As[cur^1][a][q4] = pv;
            Bs[cur^1][kq+0][rw] = bv.x; Bs[cur^1][kq+1][rw] = bv.y;
            Bs[cur^1][kq+2][rw] = bv.z; Bs[cur^1][kq+3][rw] = bv.w;
        }
        __syncthreads();
    }
    UNPACK_ACC()   // acc[i][j] = M[g][h]

    const float* cb = g_c + b*H_;
    float local = 0.f;
    #pragma unroll
    for (int i = 0; i < 4; i++){
        int g = g0 + ty*4 + i;
        float cg = cb[g];
        float4 P4  = *(const float4*)&g_P[g*H_ + h0 + tx*4];
        float4 Q4  = *(const float4*)&g_Q[g*H_ + h0 + tx*4];
        float4 A4  = *(const float4*)&A2b[g*H_ + h0 + tx*4];
        float pr[4] = {P4.x, P4.y, P4.z, P4.w};
        float qr[4] = {Q4.x, Q4.y, Q4.z, Q4.w};
        float ar[4] = {A4.x, A4.y, A4.z, A4.w};
        #pragma unroll
        for (int j = 0; j < 4; j++){
            int hcol = h0 + tx*4 + j;
            float wgt = diag ? ((hcol > g) ? 2.f : ((hcol == g) ? 1.f : 0.f)) : 2.f;
            float a2t = Ts[tx*4+j][ty*4+i];
            local += wgt*cg*cb[hcol]*pr[j]*(qr[j]*acc[i][j] + ar[j]*a2t);
        }
    }
    __shared__ float red[256];
    red[tid] = local;
    __syncthreads();
    for (int st = 128; st > 0; st >>= 1){
        if (tid < st) red[tid] += red[tid + st];
        __syncthreads();
    }
    __shared__ unsigned int is_last;
    if (tid == 0){
        g_part[b*10 + ti] = red[0];
        __threadfence();
        is_last = (atomicAdd(&g_cnt[b], 1u) == 9u);
    }
    __syncthreads();

    if (is_last && tid < N_){
        float sum = 0.f;
        #pragma unroll
        for (int i = 0; i < 10; i++) sum += g_part[b*10 + i];
        float nrm = sqrtf(fmaxf(2.f*sum, 0.f));
        float vn  = g_vn[b];
        float v   = state[(B_+b)*N_ + tid];
        float dev = state[b*N_ + tid];
        float aout = -(g_Avec[b*N_ + tid] - 0.5f*g_Cvec[b*N_ + tid])
                     / ((nrm + 1e-6f) * (vn + 1e-6f));
        out[b*N_ + tid]       = v;
        out[(B_+b)*N_ + tid]  = aout - 0.1f*dev;
    }
}

// -------- launch --------
extern "C" void kernel_launch(void* const* d_in, const int* in_sizes, int n_in,
                              void* d_out, int out_size){
    const float* t     = (const float*)d_in[0];
    const float* state = (const float*)d_in[1];
    const float* x0    = (const float*)d_in[2];
    const float* x1    = (const float*)d_in[3];
    const float* W1    = (const float*)d_in[4];
    const float* b1    = (const float*)d_in[5];
    const float* W2    = (const float*)d_in[6];
    float* out = (float*)d_out;

    k_tr    <<<64,            256>>>(W1, W2);
    k_stage1<<<48,            256>>>(W1, W2, t, state, x0, x1, b1);
    k_A2    <<<dim3(4,4,B_),  256>>>();
    k_nrm   <<<dim3(10,1,B_), 256>>>(state, out);
}

// round 13
// speedup vs baseline: 1.0580x; 1.0580x over previous
#include <cuda_runtime.h>
#include <math.h>

#define N_ 128
#define H_ 256
#define B_ 16

// -------- device scratch --------
__device__ float g_P[H_*H_];        // W1^T W1
__device__ float g_Q[H_*H_];        // W2 W2^T
__device__ float g_W1T[H_*N_];      // W1T[h*N+i] = W1[i*H+h]
__device__ float g_W2T[N_*H_];      // W2T[k*H+h] = W2[h*N+k]
__device__ float g_s[B_*H_];
__device__ float g_c[B_*H_];
__device__ float g_Avec[B_*N_];
__device__ float g_Cvec[B_*N_];
__device__ float g_vn[B_];
__device__ float g_A2[B_*H_*H_];    // A2 = P S Q per sample
__device__ float g_part[B_*20];     // nrm^2/2 partials: [b][tile*2+ka]
__device__ unsigned int g_cnt[B_];  // last-block-done counters

#define FFMA2(d, a, b) \
    asm("fma.rn.f32x2 %0, %1, %2, %0;" : "+l"(d) : "l"(a), "l"(b))
#define DUP2(d, f) \
    asm("mov.b64 %0, {%1, %1};" : "=l"(d) : "f"(f))
#define UNPK2(lo, hi, d) \
    asm("mov.b64 {%0, %1}, %2;" : "=f"(lo), "=f"(hi) : "l"(d))

#define MICRO_STEP_F32X2(As_, Bs_)                                      \
    {   float4 ra = *(const float4*)&As_[k][ty*4];                      \
        ulonglong2 rbp = *(const ulonglong2*)&Bs_[k][tx*4];             \
        unsigned long long ad0, ad1, ad2, ad3;                          \
        DUP2(ad0, ra.x); DUP2(ad1, ra.y);                               \
        DUP2(ad2, ra.z); DUP2(ad3, ra.w);                               \
        FFMA2(accp[0][0], ad0, rbp.x); FFMA2(accp[0][1], ad0, rbp.y);   \
        FFMA2(accp[1][0], ad1, rbp.x); FFMA2(accp[1][1], ad1, rbp.y);   \
        FFMA2(accp[2][0], ad2, rbp.x); FFMA2(accp[2][1], ad2, rbp.y);   \
        FFMA2(accp[3][0], ad3, rbp.x); FFMA2(accp[3][1], ad3, rbp.y);   \
    }

#define UNPACK_ACC()                                                    \
    float acc[4][4];                                                    \
    _Pragma("unroll")                                                   \
    for (int i = 0; i < 4; i++){                                        \
        UNPK2(acc[i][0], acc[i][1], accp[i][0]);                        \
        UNPK2(acc[i][2], acc[i][3], accp[i][1]);                        \
    }

// ==================== kernel 0: transposes ====================
__global__ void __launch_bounds__(256) k_tr(const float* __restrict__ W1,
                                            const float* __restrict__ W2){
    __shared__ float ts[32][33];
    int bid = blockIdx.x;
    int tid = threadIdx.x;
    int r0 = tid >> 5, cc = tid & 31;
    if (bid < 32){
        int ti = bid >> 3, th = bid & 7;
        #pragma unroll
        for (int r = r0; r < 32; r += 8)
            ts[r][cc] = W1[(ti*32 + r)*H_ + th*32 + cc];
        __syncthreads();
        #pragma unroll
        for (int r = r0; r < 32; r += 8)
            g_W1T[(th*32 + r)*N_ + ti*32 + cc] = ts[cc][r];
    } else {
        int b2 = bid - 32;
        int th = b2 >> 2, tk = b2 & 3;
        #pragma unroll
        for (int r = r0; r < 32; r += 8)
            ts[r][cc] = W2[(th*32 + r)*N_ + tk*32 + cc];
        __syncthreads();
        #pragma unroll
        for (int r = r0; r < 32; r += 8)
            g_W2T[(tk*32 + r)*H_ + th*32 + cc] = ts[cc][r];
    }
}

// ==================== stage 1: fused P/Q GEMM + vectors ====================
__global__ void __launch_bounds__(256) k_stage1(
        const float* __restrict__ W1, const float* __restrict__ W2,
        const float* __restrict__ tptr, const float* __restrict__ state,
        const float* __restrict__ x0,  const float* __restrict__ x1,
        const float* __restrict__ b1){
    int bid = blockIdx.x;
    int tid = threadIdx.x;

    if (bid < 32){
        int z = bid >> 4, tile = bid & 15;
        int g0 = (tile >> 2)*64, h0 = (tile & 3)*64;
        __shared__ float As[16][68];
        __shared__ float Bs[16][68];
        int ty = tid >> 4, tx = tid & 15;
        unsigned long long accp[4][2] = {{0ull,0ull},{0ull,0ull},{0ull,0ull},{0ull,0ull}};

        for (int a0 = 0; a0 < N_; a0 += 16){
            if (z == 0){
                int a = tid >> 4, q4 = (tid & 15)*4;
                *(float4*)&As[a][q4] = *(const float4*)&W1[(a0+a)*H_ + g0 + q4];
                *(float4*)&Bs[a][q4] = *(const float4*)&W1[(a0+a)*H_ + h0 + q4];
            } else {
                int gg = tid >> 2, kq = (tid & 3)*4;
                float4 av = *(const float4*)&W2[(g0+gg)*N_ + a0 + kq];
                float4 bv = *(const float4*)&W2[(h0+gg)*N_ + a0 + kq];
                As[kq+0][gg] = av.x; As[kq+1][gg] = av.y;
                As[kq+2][gg] = av.z; As[kq+3][gg] = av.w;
                Bs[kq+0][gg] = bv.x; Bs[kq+1][gg] = bv.y;
                Bs[kq+2][gg] = bv.z; Bs[kq+3][gg] = bv.w;
            }
            __syncthreads();
            #pragma unroll
            for (int k = 0; k < 16; k++) MICRO_STEP_F32X2(As, Bs)
            __syncthreads();
        }
        UNPACK_ACC()
        float* dst = (z == 0) ? g_P : g_Q;
        #pragma unroll
        for (int i = 0; i < 4; i++){
            float4 o = make_float4(acc[i][0], acc[i][1], acc[i][2], acc[i][3]);
            *(float4*)&dst[(g0+ty*4+i)*H_ + h0 + tx*4] = o;
        }
        return;
    }

    // ---- per-sample vector pipeline: forced-MLP register batches ----
    int b = bid - 32;
    __shared__ float xs[N_], vs[N_], red[N_];
    __shared__ float swv[H_], cwy[H_], pvs[H_], cwz[H_];
    __shared__ float r1p[2][N_], r2p[2][N_], r1s[N_], r2s[N_];
    __shared__ float Ap[2][N_], Cp[2][N_];

    float tval = *tptr;
    float window = 4.f * tval * (1.f - tval);
    if (tid < N_){
        float dev = state[b*N_ + tid];
        float v   = state[(B_+b)*N_ + tid];
        float x0v = x0[b*N_ + tid];
        xs[tid] = x0v + tval*(x1[b*N_ + tid] - x0v) + window*dev;
        vs[tid] = v;
        red[tid] = v*v;
    }
    __syncthreads();

    if (tid < 32){
        float a0 = red[tid] + red[tid+32] + red[tid+64] + red[tid+96];
        #pragma unroll
        for (int o = 16; o; o >>= 1) a0 += __shfl_xor_sync(0xffffffffu, a0, o);
        if (tid == 0) g_vn[b] = sqrtf(a0);
    }

    int h = tid;
    float u = 0.f, y = 0.f, w = 0.f;
    for (int k0 = 0; k0 < N_; k0 += 16){
        float wb[16], tb[16];
        #pragma unroll
        for (int j = 0; j < 16; j++) wb[j] = W1[(k0+j)*H_ + h];
        #pragma unroll
        for (int j = 0; j < 16; j++) tb[j] = g_W2T[(k0+j)*H_ + h];
        #pragma unroll
        for (int j = 0; j < 16; j++){
            u += xs[k0+j]*wb[j];
            y += vs[k0+j]*wb[j];
            w += vs[k0+j]*tb[j];
        }
    }
    float th = tanhf(u + b1[h]);
    float s = 1.f - th*th;
    float c = -2.f*th*s;
    g_s[b*H_ + h] = s;
    g_c[b*H_ + h] = c;
    swv[h] = s*w;
    cwy[h] = c*w*y;
    __syncthreads();

    {
        int kk = tid & 127, half = tid >> 7;
        float s1 = 0.f, s2 = 0.f;
        for (int j0 = 0; j0 < 128; j0 += 16){
            float wb[16];
            #pragma unroll
            for (int j = 0; j < 16; j++) wb[j] = g_W1T[(half*128 + j0 + j)*N_ + kk];
            #pragma unroll
            for (int j = 0; j < 16; j++){
                s1 += wb[j]*swv[half*128 + j0 + j];
                s2 += wb[j]*cwy[half*128 + j0 + j];
            }
        }
        r1p[half][kk] = s1;
        r2p[half][kk] = s2;
    }
    __syncthreads();
    if (tid < N_){
        r1s[tid] = r1p[0][tid] + r1p[1][tid];
        r2s[tid] = r2p[0][tid] + r2p[1][tid];
    }
    __syncthreads();

    float z = 0.f, q2 = 0.f;
    for (int k0 = 0; k0 < N_; k0 += 16){
        float wb[16];
        #pragma unroll
        for (int j = 0; j < 16; j++) wb[j] = W1[(k0+j)*H_ + h];
        #pragma unroll
        for (int j = 0; j < 16; j++){
            z  += wb[j]*r1s[k0+j];
            q2 += wb[j]*r2s[k0+j];
        }
    }
    pvs[h] = c*y*z + s*q2;
    cwz[h] = c*w*z;
    __syncthreads();

    {
        int i = tid & 127, hf = tid >> 7;
        float A = 0.f, Cc = 0.f;
        for (int j0 = 0; j0 < 128; j0 += 16){
            float wa[16], wc[16];
            #pragma unroll
            for (int j = 0; j < 16; j++) wa[j] = W2[(hf*128 + j0 + j)*N_ + i];
            #pragma unroll
            for (int j = 0; j < 16; j++) wc[j] = g_W1T[(hf*128 + j0 + j)*N_ + i];
            #pragma unroll
            for (int j = 0; j < 16; j++){
                A  += wa[j]*pvs[hf*128 + j0 + j];
                Cc += wc[j]*cwz[hf*128 + j0 + j];
            }
        }
        Ap[hf][i] = A;
        Cp[hf][i] = Cc;
    }
    __syncthreads();
    if (tid < N_){
        g_Avec[b*N_ + tid] = Ap[0][tid] + Ap[1][tid];
        g_Cvec[b*N_ + tid] = 2.f*(Cp[0][tid] + Cp[1][tid]);
    }
}

// ==================== stage 2: A2[b] = P diag(s) Q (double-buffered) ====================
__global__ void __launch_bounds__(256) k_A2(){
    int b  = blockIdx.z;
    int g0 = blockIdx.y*64, h0 = blockIdx.x*64;
    int tid = threadIdx.x;
    if (blockIdx.x == 0 && blockIdx.y == 0 && tid == 0) g_cnt[b] = 0;
    int ty = tid >> 4, tx = tid & 15;
    __shared__ float Ps[2][16][68];
    __shared__ float Qs[2][16][68];
    __shared__ float ssm[H_];
    ssm[tid] = g_s[b*H_ + tid];
    unsigned long long accp[4][2] = {{0ull,0ull},{0ull,0ull},{0ull,0ull},{0ull,0ull}};

    int a = tid >> 4, q4 = (tid & 15)*4;
    float4 pv = *(const float4*)&g_P[a*H_ + g0 + q4];     // tile 0 (P symmetric)
    float4 qv = *(const float4*)&g_Q[a*H_ + h0 + q4];
    __syncthreads();                                      // ssm ready
    {
        float sa = ssm[a];
        *(float4*)&Ps[0][a][q4] = pv;
        qv.x *= sa; qv.y *= sa; qv.z *= sa; qv.w *= sa;
        *(float4*)&Qs[0][a][q4] = qv;
    }
    __syncthreads();

    for (int t = 0; t < 16; t++){
        int cur = t & 1;
        if (t < 15){
            pv = *(const float4*)&g_P[((t+1)*16 + a)*H_ + g0 + q4];
            qv = *(const float4*)&g_Q[((t+1)*16 + a)*H_ + h0 + q4];
        }
        #pragma unroll
        for (int k = 0; k < 16; k++) MICRO_STEP_F32X2(Ps[cur], Qs[cur])
        if (t < 15){
            float sa = ssm[(t+1)*16 + a];
            *(float4*)&Ps[cur^1][a][q4] = pv;
            qv.x *= sa; qv.y *= sa; qv.z *= sa; qv.w *= sa;
            *(float4*)&Qs[cur^1][a][q4] = qv;
        }
        __syncthreads();
    }
    UNPACK_ACC()
    float* dst = g_A2 + b*H_*H_;
    #pragma unroll
    for (int i = 0; i < 4; i++){
        float4 o = make_float4(acc[i][0], acc[i][1], acc[i][2], acc[i][3]);
        *(float4*)&dst[(g0+ty*4+i)*H_ + h0 + tx*4] = o;
    }
}

// ========== stage 3: M = P diag(s) A2^T, upper tiles x split-K2 ==========
// f(g,h) = c_g c_h P_gh (Q_gh M_gh + A2_gh A2_hg) symmetric in (g,h).
// grid (10, 2, B): x = upper tile, y = K half. Term1 linear in K-halves;
// Term2 + mirror tile only in ka==0 block. 20 partials per sample.
__global__ void __launch_bounds__(256) k_nrm(const float* __restrict__ state,
                                             float* __restrict__ out){
    const int gt_t[10] = {0,0,0,0,1,1,1,2,2,3};
    const int ht_t[10] = {0,1,2,3,1,2,3,2,3,3};
    int b  = blockIdx.z;
    int ti = blockIdx.x;
    int ka = blockIdx.y;
    int g0 = gt_t[ti]*64, h0 = ht_t[ti]*64;
    int abase = ka*128;
    bool diag = (g0 == h0);
    int tid = threadIdx.x;
    int ty = tid >> 4, tx = tid & 15;
    __shared__ float As[2][16][68];
    __shared__ float Bs[2][16][68];
    __shared__ float Ts[64][65];       // mirror tile A2[h0.., g0..] (ka==0 only)
    __shared__ float ssm[H_];
    ssm[tid] = g_s[b*H_ + tid];
    unsigned long long accp[4][2] = {{0ull,0ull},{0ull,0ull},{0ull,0ull},{0ull,0ull}};

    const float* A2b = g_A2 + b*H_*H_;
    int a  = tid >> 4, q4 = (tid & 15)*4;
    int rw = tid >> 2, kq = (tid & 3)*4;

    if (ka == 0){
        #pragma unroll
        for (int p = 0; p < 4; p++){
            int f = tid + p*256;
            int row = f >> 4, c4 = (f & 15)*4;
            float4 tv = *(const float4*)&A2b[(h0+row)*H_ + g0 + c4];
            Ts[row][c4+0] = tv.x; Ts[row][c4+1] = tv.y;
            Ts[row][c4+2] = tv.z; Ts[row][c4+3] = tv.w;
        }
    }

    float4 pv = *(const float4*)&g_P[(abase + a)*H_ + g0 + q4];
    float4 bv = *(const float4*)&A2b[(h0+rw)*H_ + abase + kq];
    __syncthreads();
    {
        float sa = ssm[abase + a];
        pv.x *= sa; pv.y *= sa; pv.z *= sa; pv.w *= sa;
        *(float4*)&As[0][a][q4] = pv;
        Bs[0][kq+0][rw] = bv.x; Bs[0][kq+1][rw] = bv.y;
        Bs[0][kq+2][rw] = bv.z; Bs[0][kq+3][rw] = bv.w;
    }
    __syncthreads();

    for (int t = 0; t < 8; t++){
        int cur = t & 1;
        if (t < 7){
            pv = *(const float4*)&g_P[(abase + (t+1)*16 + a)*H_ + g0 + q4];
            bv = *(const float4*)&A2b[(h0+rw)*H_ + abase + (t+1)*16 + kq];
        }
        #pragma unroll
        for (int k = 0; k < 16; k++) MICRO_STEP_F32X2(As[cur], Bs[cur])
        if (t < 7){
            float sa = ssm[abase + (t+1)*16 + a];
            pv.x *= sa; pv.y *= sa; pv.z *= sa; pv.w *= sa;
            *(float4*)&As[cur^1][a][q4] = pv;
            Bs[cur^1][kq+0][rw] = bv.x; Bs[cur^1][kq+1][rw] = bv.y;
            Bs[cur^1][kq+2][rw] = bv.z; Bs[cur^1][kq+3][rw] = bv.w;
        }
        __syncthreads();
    }
    UNPACK_ACC()   // acc[i][j] = partial M[g][h] over this K half

    const float* cb = g_c + b*H_;
    float local = 0.f;
    #pragma unroll
    for (int i = 0; i < 4; i++){
        int g = g0 + ty*4 + i;
        float cg = cb[g];
        float4 P4  = *(const float4*)&g_P[g*H_ + h0 + tx*4];
        float4 Q4  = *(const float4*)&g_Q[g*H_ + h0 + tx*4];
        float pr[4] = {P4.x, P4.y, P4.z, P4.w};
        float qr[4] = {Q4.x, Q4.y, Q4.z, Q4.w};
        if (ka == 0){
            float4 A4 = *(const float4*)&A2b[g*H_ + h0 + tx*4];
            float ar[4] = {A4.x, A4.y, A4.z, A4.w};
            #pragma unroll
            for (int j = 0; j < 4; j++){
                int hcol = h0 + tx*4 + j;
                float wgt = diag ? ((hcol > g) ? 2.f : ((hcol == g) ? 1.f : 0.f)) : 2.f;
                float a2t = Ts[tx*4+j][ty*4+i];
                local += wgt*cg*cb[hcol]*pr[j]*(qr[j]*acc[i][j] + ar[j]*a2t);
            }
        } else {
            #pragma unroll
            for (int j = 0; j < 4; j++){
                int hcol = h0 + tx*4 + j;
                float wgt = diag ? ((hcol > g) ? 2.f : ((hcol == g) ? 1.f : 0.f)) : 2.f;
                local += wgt*cg*cb[hcol]*pr[j]*qr[j]*acc[i][j];
            }
        }
    }
    __shared__ float red[256];
    red[tid] = local;
    __syncthreads();
    for (int st = 128; st > 0; st >>= 1){
        if (tid < st) red[tid] += red[tid + st];
        __syncthreads();
    }
    __shared__ unsigned int is_last;
    if (tid == 0){
        g_part[b*20 + ti*2 + ka] = red[0];
        __threadfence();
        is_last = (atomicAdd(&g_cnt[b], 1u) == 19u);
    }
    __syncthreads();

    if (is_last && tid < N_){
        float sum = 0.f;
        #pragma unroll
        for (int i = 0; i < 20; i++) sum += g_part[b*20 + i];
        float nrm = sqrtf(fmaxf(2.f*sum, 0.f));
        float vn  = g_vn[b];
        float v   = state[(B_+b)*N_ + tid];
        float dev = state[b*N_ + tid];
        float aout = -(g_Avec[b*N_ + tid] - 0.5f*g_Cvec[b*N_ + tid])
                     / ((nrm + 1e-6f) * (vn + 1e-6f));
        out[b*N_ + tid]       = v;
        out[(B_+b)*N_ + tid]  = aout - 0.1f*dev;
    }
}

// -------- launch --------
extern "C" void kernel_launch(void* const* d_in, const int* in_sizes, int n_in,
                              void* d_out, int out_size){
    const float* t     = (const float*)d_in[0];
    const float* state = (const float*)d_in[1];
    const float* x0    = (const float*)d_in[2];
    const float* x1    = (const float*)d_in[3];
    const float* W1    = (const float*)d_in[4];
    const float* b1    = (const float*)d_in[5];
    const float* W2    = (const float*)d_in[6];
    float* out = (float*)d_out;

    k_tr    <<<64,            256>>>(W1, W2);
    k_stage1<<<48,            256>>>(W1, W2, t, state, x0, x1, b1);
    k_A2    <<<dim3(4,4,B_),  256>>>();
    k_nrm   <<<dim3(10,2,B_), 256>>>(state, out);
}

// round 14
// speedup vs baseline: 1.0625x; 1.0043x over previous
#include <cuda_runtime.h>
#include <math.h>

#define N_ 128
#define H_ 256
#define B_ 16

// -------- device scratch --------
__device__ float g_P[H_*H_];        // W1^T W1
__device__ float g_Q[H_*H_];        // W2 W2^T
__device__ float g_s[B_*H_];
__device__ float g_c[B_*H_];
__device__ float g_Avec[B_*N_];
__device__ float g_Cvec[B_*N_];
__device__ float g_vn[B_];
__device__ float g_A2[2*B_*H_*H_];  // split-K partials: [ka*B+b][g][h]
__device__ float g_part[B_*20];     // nrm^2/2 partials: [b][tile*2+ka]
__device__ unsigned int g_cnt[B_];  // last-block-done counters

#define FFMA2(d, a, b) \
    asm("fma.rn.f32x2 %0, %1, %2, %0;" : "+l"(d) : "l"(a), "l"(b))
#define DUP2(d, f) \
    asm("mov.b64 %0, {%1, %1};" : "=l"(d) : "f"(f))
#define UNPK2(lo, hi, d) \
    asm("mov.b64 {%0, %1}, %2;" : "=f"(lo), "=f"(hi) : "l"(d))

#define MICRO_STEP_F32X2(As_, Bs_)                                      \
    {   float4 ra = *(const float4*)&As_[k][ty*4];                      \
        ulonglong2 rbp = *(const ulonglong2*)&Bs_[k][tx*4];             \
        unsigned long long ad0, ad1, ad2, ad3;                          \
        DUP2(ad0, ra.x); DUP2(ad1, ra.y);                               \
        DUP2(ad2, ra.z); DUP2(ad3, ra.w);                               \
        FFMA2(accp[0][0], ad0, rbp.x); FFMA2(accp[0][1], ad0, rbp.y);   \
        FFMA2(accp[1][0], ad1, rbp.x); FFMA2(accp[1][1], ad1, rbp.y);   \
        FFMA2(accp[2][0], ad2, rbp.x); FFMA2(accp[2][1], ad2, rbp.y);   \
        FFMA2(accp[3][0], ad3, rbp.x); FFMA2(accp[3][1], ad3, rbp.y);   \
    }

#define UNPACK_ACC()                                                    \
    float acc[4][4];                                                    \
    _Pragma("unroll")                                                   \
    for (int i = 0; i < 4; i++){                                        \
        UNPK2(acc[i][0], acc[i][1], accp[i][0]);                        \
        UNPK2(acc[i][2], acc[i][3], accp[i][1]);                        \
    }

// ==================== stage 1: fused P/Q GEMM + vectors ====================
// blocks 0..15: P tiles, 16..31: Q tiles, 32..47: per-sample vectors.
__global__ void __launch_bounds__(256) k_stage1(
        const float* __restrict__ W1, const float* __restrict__ W2,
        const float* __restrict__ tptr, const float* __restrict__ state,
        const float* __restrict__ x0,  const float* __restrict__ x1,
        const float* __restrict__ b1){
    int bid = blockIdx.x;
    int tid = threadIdx.x;

    if (bid < 32){
        // ---- P = W1^T W1 (z=0) or Q = W2 W2^T (z=1), double-buffered ----
        int z = bid >> 4, tile = bid & 15;
        int g0 = (tile >> 2)*64, h0 = (tile & 3)*64;
        __shared__ float As[2][16][68];
        __shared__ float Bs[2][16][68];
        int ty = tid >> 4, tx = tid & 15;
        unsigned long long accp[4][2] = {{0ull,0ull},{0ull,0ull},{0ull,0ull},{0ull,0ull}};

        int la = tid >> 4, lq4 = (tid & 15)*4;   // z==0 mapping
        int gg = tid >> 2, kq = (tid & 3)*4;     // z==1 mapping
        float4 av, bv;
        if (z == 0){
            av = *(const float4*)&W1[la*H_ + g0 + lq4];
            bv = *(const float4*)&W1[la*H_ + h0 + lq4];
        } else {
            av = *(const float4*)&W2[(g0+gg)*N_ + kq];
            bv = *(const float4*)&W2[(h0+gg)*N_ + kq];
        }
        if (z == 0){
            *(float4*)&As[0][la][lq4] = av;
            *(float4*)&Bs[0][la][lq4] = bv;
        } else {
            As[0][kq+0][gg] = av.x; As[0][kq+1][gg] = av.y;
            As[0][kq+2][gg] = av.z; As[0][kq+3][gg] = av.w;
            Bs[0][kq+0][gg] = bv.x; Bs[0][kq+1][gg] = bv.y;
            Bs[0][kq+2][gg] = bv.z; Bs[0][kq+3][gg] = bv.w;
        }
        __syncthreads();

        for (int t = 0; t < 8; t++){
            int cur = t & 1;
            if (t < 7){
                int a0 = (t+1)*16;
                if (z == 0){
                    av = *(const float4*)&W1[(a0+la)*H_ + g0 + lq4];
                    bv = *(const float4*)&W1[(a0+la)*H_ + h0 + lq4];
                } else {
                    av = *(const float4*)&W2[(g0+gg)*N_ + a0 + kq];
                    bv = *(const float4*)&W2[(h0+gg)*N_ + a0 + kq];
                }
            }
            #pragma unroll
            for (int k = 0; k < 16; k++) MICRO_STEP_F32X2(As[cur], Bs[cur])
            if (t < 7){
                if (z == 0){
                    *(float4*)&As[cur^1][la][lq4] = av;
                    *(float4*)&Bs[cur^1][la][lq4] = bv;
                } else {
                    As[cur^1][kq+0][gg] = av.x; As[cur^1][kq+1][gg] = av.y;
                    As[cur^1][kq+2][gg] = av.z; As[cur^1][kq+3][gg] = av.w;
                    Bs[cur^1][kq+0][gg] = bv.x; Bs[cur^1][kq+1][gg] = bv.y;
                    Bs[cur^1][kq+2][gg] = bv.z; Bs[cur^1][kq+3][gg] = bv.w;
                }
            }
            __syncthreads();
        }
        UNPACK_ACC()
        float* dst = (z == 0) ? g_P : g_Q;
        #pragma unroll
        for (int i = 0; i < 4; i++){
            float4 o = make_float4(acc[i][0], acc[i][1], acc[i][2], acc[i][3]);
            *(float4*)&dst[(g0+ty*4+i)*H_ + h0 + tx*4] = o;
        }
        return;
    }

    // ---- per-sample vector pipeline: row-major per-thread dots, no transposes ----
    int b = bid - 32;
    __shared__ float xs[N_], vs[N_], red[N_];
    __shared__ float swv[H_], cwy[H_], pvs[H_], cwz[H_];
    __shared__ float r1p[2][N_], r2p[2][N_], r1s[N_], r2s[N_];
    __shared__ float Ap[2][N_], Cp[2][N_];

    float tval = *tptr;
    float window = 4.f * tval * (1.f - tval);
    if (tid < N_){
        float dev = state[b*N_ + tid];
        float v   = state[(B_+b)*N_ + tid];
        float x0v = x0[b*N_ + tid];
        xs[tid] = x0v + tval*(x1[b*N_ + tid] - x0v) + window*dev;
        vs[tid] = v;
        red[tid] = v*v;
    }
    __syncthreads();

    if (tid < 32){
        float a0 = red[tid] + red[tid+32] + red[tid+64] + red[tid+96];
        #pragma unroll
        for (int o = 16; o; o >>= 1) a0 += __shfl_xor_sync(0xffffffffu, a0, o);
        if (tid == 0) g_vn[b] = sqrtf(a0);
    }

    int h = tid;
    // phase B: u,y via W1 columns (coalesced); w via W2 row h (per-thread float4)
    float u = 0.f, y = 0.f, w = 0.f;
    {
        const float* w2r = W2 + h*N_;
        for (int k0 = 0; k0 < N_; k0 += 16){
            float wb[16], tb[16];
            #pragma unroll
            for (int j = 0; j < 16; j++) wb[j] = W1[(k0+j)*H_ + h];
            float4 t0 = *(const float4*)&w2r[k0];
            float4 t1 = *(const float4*)&w2r[k0+4];
            float4 t2 = *(const float4*)&w2r[k0+8];
            float4 t3 = *(const float4*)&w2r[k0+12];
            tb[0]=t0.x; tb[1]=t0.y; tb[2]=t0.z; tb[3]=t0.w;
            tb[4]=t1.x; tb[5]=t1.y; tb[6]=t1.z; tb[7]=t1.w;
            tb[8]=t2.x; tb[9]=t2.y; tb[10]=t2.z; tb[11]=t2.w;
            tb[12]=t3.x; tb[13]=t3.y; tb[14]=t3.z; tb[15]=t3.w;
            #pragma unroll
            for (int j = 0; j < 16; j++){
                u += xs[k0+j]*wb[j];
                y += vs[k0+j]*wb[j];
                w += vs[k0+j]*tb[j];
            }
        }
    }
    float th = tanhf(u + b1[h]);
    float s = 1.f - th*th;
    float c = -2.f*th*s;
    g_s[b*H_ + h] = s;
    g_c[b*H_ + h] = c;
    swv[h] = s*w;
    cwy[h] = c*w*y;
    __syncthreads();

    // phase C: r1 = W1*swv, r2 = W1*cwy via W1 row kk (2 threads per output)
    {
        int kk = tid & 127, half = tid >> 7;
        const float* w1r = W1 + kk*H_ + half*128;
        float s1 = 0.f, s2 = 0.f;
        for (int j0 = 0; j0 < 128; j0 += 16){
            float wb[16];
            float4 t0 = *(const float4*)&w1r[j0];
            float4 t1 = *(const float4*)&w1r[j0+4];
            float4 t2 = *(const float4*)&w1r[j0+8];
            float4 t3 = *(const float4*)&w1r[j0+12];
            wb[0]=t0.x; wb[1]=t0.y; wb[2]=t0.z; wb[3]=t0.w;
            wb[4]=t1.x; wb[5]=t1.y; wb[6]=t1.z; wb[7]=t1.w;
            wb[8]=t2.x; wb[9]=t2.y; wb[10]=t2.z; wb[11]=t2.w;
            wb[12]=t3.x; wb[13]=t3.y; wb[14]=t3.z; wb[15]=t3.w;
            #pragma unroll
            for (int j = 0; j < 16; j++){
                s1 += wb[j]*swv[half*128 + j0 + j];
                s2 += wb[j]*cwy[half*128 + j0 + j];
            }
        }
        r1p[half][kk] = s1;
        r2p[half][kk] = s2;
    }
    __syncthreads();
    if (tid < N_){
        r1s[tid] = r1p[0][tid] + r1p[1][tid];
        r2s[tid] = r2p[0][tid] + r2p[1][tid];
    }
    __syncthreads();

    // phase D: z = W1^T r1, q2 = W1^T r2 (coalesced W1 columns)
    float z = 0.f, q2 = 0.f;
    for (int k0 = 0; k0 < N_; k0 += 16){
        float wb[16];
        #pragma unroll
        for (int j = 0; j < 16; j++) wb[j] = W1[(k0+j)*H_ + h];
        #pragma unroll
        for (int j = 0; j < 16; j++){
            z  += wb[j]*r1s[k0+j];
            q2 += wb[j]*r2s[k0+j];
        }
    }
    pvs[h] = c*y*z + s*q2;
    cwz[h] = c*w*z;
    __syncthreads();

    // phase E: A = W2^T pv (W2 columns, coalesced), C = W1 row i
    {
        int i = tid & 127, hf = tid >> 7;
        const float* w1r = W1 + i*H_ + hf*128;
        float A = 0.f, Cc = 0.f;
        for (int j0 = 0; j0 < 128; j0 += 16){
            float wa[16], wc[16];
            #pragma unroll
            for (int j = 0; j < 16; j++) wa[j] = W2[(hf*128 + j0 + j)*N_ + i];
            float4 t0 = *(const float4*)&w1r[j0];
            float4 t1 = *(const float4*)&w1r[j0+4];
            float4 t2 = *(const float4*)&w1r[j0+8];
            float4 t3 = *(const float4*)&w1r[j0+12];
            wc[0]=t0.x; wc[1]=t0.y; wc[2]=t0.z; wc[3]=t0.w;
            wc[4]=t1.x; wc[5]=t1.y; wc[6]=t1.z; wc[7]=t1.w;
            wc[8]=t2.x; wc[9]=t2.y; wc[10]=t2.z; wc[11]=t2.w;
            wc[12]=t3.x; wc[13]=t3.y; wc[14]=t3.z; wc[15]=t3.w;
            #pragma unroll
            for (int j = 0; j < 16; j++){
                A  += wa[j]*pvs[hf*128 + j0 + j];
                Cc += wc[j]*cwz[hf*128 + j0 + j];
            }
        }
        Ap[hf][i] = A;
        Cp[hf][i] = Cc;
    }
    __syncthreads();
    if (tid < N_){
        g_Avec[b*N_ + tid] = Ap[0][tid] + Ap[1][tid];
        g_Cvec[b*N_ + tid] = 2.f*(Cp[0][tid] + Cp[1][tid]);
    }
}

// ========== stage 2: A2 partial = P[:,ka] diag(s) Q[ka,:] (split-K x2, pipelined) ==========
__global__ void __launch_bounds__(256) k_A2(){
    int zz = blockIdx.z;
    int b = zz >> 1, ka = zz & 1;
    int g0 = blockIdx.y*64, h0 = blockIdx.x*64;
    int tid = threadIdx.x;
    if (blockIdx.x == 0 && blockIdx.y == 0 && ka == 0 && tid == 0) g_cnt[b] = 0;
    int ty = tid >> 4, tx = tid & 15;
    __shared__ float Ps[2][16][68];
    __shared__ float Qs[2][16][68];
    __shared__ float ssm[H_];
    ssm[tid] = g_s[b*H_ + tid];
    unsigned long long accp[4][2] = {{0ull,0ull},{0ull,0ull},{0ull,0ull},{0ull,0ull}};

    int a = tid >> 4, q4 = (tid & 15)*4;
    int abase = ka*128;
    float4 pv = *(const float4*)&g_P[(abase + a)*H_ + g0 + q4];   // P symmetric
    float4 qv = *(const float4*)&g_Q[(abase + a)*H_ + h0 + q4];
    __syncthreads();                                              // ssm ready
    {
        float sa = ssm[abase + a];
        *(float4*)&Ps[0][a][q4] = pv;
        qv.x *= sa; qv.y *= sa; qv.z *= sa; qv.w *= sa;
        *(float4*)&Qs[0][a][q4] = qv;
    }
    __syncthreads();

    for (int t = 0; t < 8; t++){
        int cur = t & 1;
        if (t < 7){
            pv = *(const float4*)&g_P[(abase + (t+1)*16 + a)*H_ + g0 + q4];
            qv = *(const float4*)&g_Q[(abase + (t+1)*16 + a)*H_ + h0 + q4];
        }
        #pragma unroll
        for (int k = 0; k < 16; k++) MICRO_STEP_F32X2(Ps[cur], Qs[cur])
        if (t < 7){
            float sa = ssm[abase + (t+1)*16 + a];
            *(float4*)&Ps[cur^1][a][q4] = pv;
            qv.x *= sa; qv.y *= sa; qv.z *= sa; qv.w *= sa;
            *(float4*)&Qs[cur^1][a][q4] = qv;
        }
        __syncthreads();
    }
    UNPACK_ACC()
    float* dst = g_A2 + (ka*B_ + b)*H_*H_;
    #pragma unroll
    for (int i = 0; i < 4; i++){
        float4 o = make_float4(acc[i][0], acc[i][1], acc[i][2], acc[i][3]);
        *(float4*)&dst[(g0+ty*4+i)*H_ + h0 + tx*4] = o;
    }
}

// ========== stage 3: M = P diag(s) A2^T, upper tiles x split-K2, A2 = lo+hi ==========
__global__ void __launch_bounds__(256) k_nrm(const float* __restrict__ state,
                                             float* __restrict__ out){
    const int gt_t[10] = {0,0,0,0,1,1,1,2,2,3};
    const int ht_t[10] = {0,1,2,3,1,2,3,2,3,3};
    int b  = blockIdx.z;
    int ti = blockIdx.x;
    int ka = blockIdx.y;
    int g0 = gt_t[ti]*64, h0 = ht_t[ti]*64;
    int abase = ka*128;
    bool diag = (g0 == h0);
    int tid = threadIdx.x;
    int ty = tid >> 4, tx = tid & 15;
    __shared__ float As[2][16][68];
    __shared__ float Bs[2][16][68];
    __shared__ float Ts[64][65];       // mirror tile (A2lo+A2hi)[h0.., g0..] (ka==0)
    __shared__ float ssm[H_];
    ssm[tid] = g_s[b*H_ + tid];
    unsigned long long accp[4][2] = {{0ull,0ull},{0ull,0ull},{0ull,0ull},{0ull,0ull}};

    const float* A2lo = g_A2 + b*H_*H_;
    const float* A2hi = g_A2 + (B_ + b)*H_*H_;
    int a  = tid >> 4, q4 = (tid & 15)*4;
    int rw = tid >> 2, kq = (tid & 3)*4;

    if (ka == 0){
        #pragma unroll
        for (int p = 0; p < 4; p++){
            int f = tid + p*256;
            int row = f >> 4, c4 = (f & 15)*4;
            float4 tl = *(const float4*)&A2lo[(h0+row)*H_ + g0 + c4];
            float4 thv = *(const float4*)&A2hi[(h0+row)*H_ + g0 + c4];
            Ts[row][c4+0] = tl.x+thv.x; Ts[row][c4+1] = tl.y+thv.y;
            Ts[row][c4+2] = tl.z+thv.z; Ts[row][c4+3] = tl.w+thv.w;
        }
    }

    float4 pv = *(const float4*)&g_P[(abase + a)*H_ + g0 + q4];
    float4 bl = *(const float4*)&A2lo[(h0+rw)*H_ + abase + kq];
    float4 bh = *(const float4*)&A2hi[(h0+rw)*H_ + abase + kq];
    __syncthreads();
    {
        float sa = ssm[abase + a];
        pv.x *= sa; pv.y *= sa; pv.z *= sa; pv.w *= sa;
        *(float4*)&As[0][a][q4] = pv;
        Bs[0][kq+0][rw] = bl.x+bh.x; Bs[0][kq+1][rw] = bl.y+bh.y;
        Bs[0][kq+2][rw] = bl.z+bh.z; Bs[0][kq+3][rw] = bl.w+bh.w;
    }
    __syncthreads();

    for (int t = 0; t < 8; t++){
        int cur = t & 1;
        if (t < 7){
            pv = *(const float4*)&g_P[(abase + (t+1)*16 + a)*H_ + g0 + q4];
            bl = *(const float4*)&A2lo[(h0+rw)*H_ + abase + (t+1)*16 + kq];
            bh = *(const float4*)&A2hi[(h0+rw)*H_ + abase + (t+1)*16 + kq];
        }
        #pragma unroll
        for (int k = 0; k < 16; k++) MICRO_STEP_F32X2(As[cur], Bs[cur])
        if (t < 7){
            float sa = ssm[abase + (t+1)*16 + a];
            pv.x *= sa; pv.y *= sa; pv.z *= sa; pv.w *= sa;
            *(float4*)&As[cur^1][a][q4] = pv;
            Bs[cur^1][kq+0][rw] = bl.x+bh.x; Bs[cur^1][kq+1][rw] = bl.y+bh.y;
            Bs[cur^1][kq+2][rw] = bl.z+bh.z; Bs[cur^1][kq+3][rw] = bl.w+bh.w;
        }
        __syncthreads();
    }
    UNPACK_ACC()   // acc[i][j] = partial M[g][h] over this K half

    const float* cb = g_c + b*H_;
    float local = 0.f;
    #pragma unroll
    for (int i = 0; i < 4; i++){
        int g = g0 + ty*4 + i;
        float cg = cb[g];
        float4 P4  = *(const float4*)&g_P[g*H_ + h0 + tx*4];
        float4 Q4  = *(const float4*)&g_Q[g*H_ + h0 + tx*4];
        float pr[4] = {P4.x, P4.y, P4.z, P4.w};
        float qr[4] = {Q4.x, Q4.y, Q4.z, Q4.w};
        if (ka == 0){
            float4 Al = *(const float4*)&A2lo[g*H_ + h0 + tx*4];
            float4 Ah = *(const float4*)&A2hi[g*H_ + h0 + tx*4];
            float ar[4] = {Al.x+Ah.x, Al.y+Ah.y, Al.z+Ah.z, Al.w+Ah.w};
            #pragma unroll
            for (int j = 0; j < 4; j++){
                int hcol = h0 + tx*4 + j;
                float wgt = diag ? ((hcol > g) ? 2.f : ((hcol == g) ? 1.f : 0.f)) : 2.f;
                float a2t = Ts[tx*4+j][ty*4+i];
                local += wgt*cg*cb[hcol]*pr[j]*(qr[j]*acc[i][j] + ar[j]*a2t);
            }
        } else {
            #pragma unroll
            for (int j = 0; j < 4; j++){
                int hcol = h0 + tx*4 + j;
                float wgt = diag ? ((hcol > g) ? 2.f : ((hcol == g) ? 1.f : 0.f)) : 2.f;
                local += wgt*cg*cb[hcol]*pr[j]*qr[j]*acc[i][j];
            }
        }
    }
    __shared__ float red[256];
    red[tid] = local;
    __syncthreads();
    for (int st = 128; st > 0; st >>= 1){
        if (tid < st) red[tid] += red[tid + st];
        __syncthreads();
    }
    __shared__ unsigned int is_last;
    if (tid == 0){
        g_part[b*20 + ti*2 + ka] = red[0];
        __threadfence();
        is_last = (atomicAdd(&g_cnt[b], 1u) == 19u);
    }
    __syncthreads();

    if (is_last && tid < N_){
        float sum = 0.f;
        #pragma unroll
        for (int i = 0; i < 20; i++) sum += g_part[b*20 + i];
        float nrm = sqrtf(fmaxf(2.f*sum, 0.f));
        float vn  = g_vn[b];
        float v   = state[(B_+b)*N_ + tid];
        float dev = state[b*N_ + tid];
        float aout = -(g_Avec[b*N_ + tid] - 0.5f*g_Cvec[b*N_ + tid])
                     / ((nrm + 1e-6f) * (vn + 1e-6f));
        out[b*N_ + tid]       = v;
        out[(B_+b)*N_ + tid]  = aout - 0.1f*dev;
    }
}

// -------- launch --------
extern "C" void kernel_launch(void* const* d_in, const int* in_sizes, int n_in,
                              void* d_out, int out_size){
    const float* t     = (const float*)d_in[0];
    const float* state = (const float*)d_in[1];
    const float* x0    = (const float*)d_in[2];
    const float* x1    = (const float*)d_in[3];
    const float* W1    = (const float*)d_in[4];
    const float* b1    = (const float*)d_in[5];
    const float* W2    = (const float*)d_in[6];
    float* out = (float*)d_out;

    k_stage1<<<48,            256>>>(W1, W2, t, state, x0, x1, b1);
    k_A2    <<<dim3(4,4,2*B_),256>>>();
    k_nrm   <<<dim3(10,2,B_), 256>>>(state, out);
}

// round 15
// speedup vs baseline: 1.1406x; 1.0734x over previous
#include <cuda_runtime.h>
#include <math.h>

#define N_ 128
#define H_ 256
#define B_ 16

// -------- device scratch --------
__device__ float g_P[H_*H_];        // W1^T W1
__device__ float g_Q[H_*H_];        // W2 W2^T
__device__ float g_s[B_*H_];
__device__ float g_c[B_*H_];
__device__ float g_Avec[B_*N_];
__device__ float g_Cvec[B_*N_];
__device__ float g_vn[B_];
__device__ float g_A2[2*B_*H_*H_];  // split-K partials: [ka*B+b][g][h]
__device__ float g_part[B_*20];     // nrm^2/2 partials: [b][tile*2+ka]
__device__ unsigned int g_cnt[B_];  // last-block-done counters

#define FFMA2(d, a, b) \
    asm("fma.rn.f32x2 %0, %1, %2, %0;" : "+l"(d) : "l"(a), "l"(b))
#define DUP2(d, f) \
    asm("mov.b64 %0, {%1, %1};" : "=l"(d) : "f"(f))
#define UNPK2(lo, hi, d) \
    asm("mov.b64 {%0, %1}, %2;" : "=f"(lo), "=f"(hi) : "l"(d))

#define MICRO_STEP_F32X2(As_, Bs_)                                      \
    {   float4 ra = *(const float4*)&As_[k][ty*4];                      \
        ulonglong2 rbp = *(const ulonglong2*)&Bs_[k][tx*4];             \
        unsigned long long ad0, ad1, ad2, ad3;                          \
        DUP2(ad0, ra.x); DUP2(ad1, ra.y);                               \
        DUP2(ad2, ra.z); DUP2(ad3, ra.w);                               \
        FFMA2(accp[0][0], ad0, rbp.x); FFMA2(accp[0][1], ad0, rbp.y);   \
        FFMA2(accp[1][0], ad1, rbp.x); FFMA2(accp[1][1], ad1, rbp.y);   \
        FFMA2(accp[2][0], ad2, rbp.x); FFMA2(accp[2][1], ad2, rbp.y);   \
        FFMA2(accp[3][0], ad3, rbp.x); FFMA2(accp[3][1], ad3, rbp.y);   \
    }

#define UNPACK_ACC()                                                    \
    float acc[4][4];                                                    \
    _Pragma("unroll")                                                   \
    for (int i = 0; i < 4; i++){                                        \
        UNPK2(acc[i][0], acc[i][1], accp[i][0]);                        \
        UNPK2(acc[i][2], acc[i][3], accp[i][1]);                        \
    }

#define LOAD16_ROW(dst, ptr)                                            \
    {   float4 t0 = *(const float4*)&(ptr)[0];                          \
        float4 t1 = *(const float4*)&(ptr)[4];                          \
        float4 t2 = *(const float4*)&(ptr)[8];                          \
        float4 t3 = *(const float4*)&(ptr)[12];                         \
        dst[0]=t0.x; dst[1]=t0.y; dst[2]=t0.z; dst[3]=t0.w;             \
        dst[4]=t1.x; dst[5]=t1.y; dst[6]=t1.z; dst[7]=t1.w;             \
        dst[8]=t2.x; dst[9]=t2.y; dst[10]=t2.z; dst[11]=t2.w;           \
        dst[12]=t3.x; dst[13]=t3.y; dst[14]=t3.z; dst[15]=t3.w;         \
    }

// ==================== stage 1: P/Q GEMM + s,c,vn only ====================
// blocks 0..15: P tiles, 16..31: Q tiles, 32..47: per-sample s/c/vn.
__global__ void __launch_bounds__(256) k_stage1(
        const float* __restrict__ W1, const float* __restrict__ W2,
        const float* __restrict__ tptr, const float* __restrict__ state,
        const float* __restrict__ x0,  const float* __restrict__ x1,
        const float* __restrict__ b1){
    int bid = blockIdx.x;
    int tid = threadIdx.x;

    if (bid < 32){
        int z = bid >> 4, tile = bid & 15;
        int g0 = (tile >> 2)*64, h0 = (tile & 3)*64;
        __shared__ float As[2][16][68];
        __shared__ float Bs[2][16][68];
        int ty = tid >> 4, tx = tid & 15;
        unsigned long long accp[4][2] = {{0ull,0ull},{0ull,0ull},{0ull,0ull},{0ull,0ull}};

        int la = tid >> 4, lq4 = (tid & 15)*4;
        int gg = tid >> 2, kq = (tid & 3)*4;
        float4 av, bv;
        if (z == 0){
            av = *(const float4*)&W1[la*H_ + g0 + lq4];
            bv = *(const float4*)&W1[la*H_ + h0 + lq4];
            *(float4*)&As[0][la][lq4] = av;
            *(float4*)&Bs[0][la][lq4] = bv;
        } else {
            av = *(const float4*)&W2[(g0+gg)*N_ + kq];
            bv = *(const float4*)&W2[(h0+gg)*N_ + kq];
            As[0][kq+0][gg] = av.x; As[0][kq+1][gg] = av.y;
            As[0][kq+2][gg] = av.z; As[0][kq+3][gg] = av.w;
            Bs[0][kq+0][gg] = bv.x; Bs[0][kq+1][gg] = bv.y;
            Bs[0][kq+2][gg] = bv.z; Bs[0][kq+3][gg] = bv.w;
        }
        __syncthreads();

        for (int t = 0; t < 8; t++){
            int cur = t & 1;
            if (t < 7){
                int a0 = (t+1)*16;
                if (z == 0){
                    av = *(const float4*)&W1[(a0+la)*H_ + g0 + lq4];
                    bv = *(const float4*)&W1[(a0+la)*H_ + h0 + lq4];
                } else {
                    av = *(const float4*)&W2[(g0+gg)*N_ + a0 + kq];
                    bv = *(const float4*)&W2[(h0+gg)*N_ + a0 + kq];
                }
            }
            #pragma unroll
            for (int k = 0; k < 16; k++) MICRO_STEP_F32X2(As[cur], Bs[cur])
            if (t < 7){
                if (z == 0){
                    *(float4*)&As[cur^1][la][lq4] = av;
                    *(float4*)&Bs[cur^1][la][lq4] = bv;
                } else {
                    As[cur^1][kq+0][gg] = av.x; As[cur^1][kq+1][gg] = av.y;
                    As[cur^1][kq+2][gg] = av.z; As[cur^1][kq+3][gg] = av.w;
                    Bs[cur^1][kq+0][gg] = bv.x; Bs[cur^1][kq+1][gg] = bv.y;
                    Bs[cur^1][kq+2][gg] = bv.z; Bs[cur^1][kq+3][gg] = bv.w;
                }
            }
            __syncthreads();
        }
        UNPACK_ACC()
        float* dst = (z == 0) ? g_P : g_Q;
        #pragma unroll
        for (int i = 0; i < 4; i++){
            float4 o = make_float4(acc[i][0], acc[i][1], acc[i][2], acc[i][3]);
            *(float4*)&dst[(g0+ty*4+i)*H_ + h0 + tx*4] = o;
        }
        return;
    }

    // ---- per-sample: x, u = W1^T x, s, c, ||v|| ----
    int b = bid - 32;
    __shared__ float xs[N_], red[N_];
    if (tid == 0) g_cnt[b] = 0;     // reset for k_nrm

    float tval = *tptr;
    float window = 4.f * tval * (1.f - tval);
    if (tid < N_){
        float dev = state[b*N_ + tid];
        float v   = state[(B_+b)*N_ + tid];
        float x0v = x0[b*N_ + tid];
        xs[tid] = x0v + tval*(x1[b*N_ + tid] - x0v) + window*dev;
        red[tid] = v*v;
    }
    __syncthreads();

    if (tid < 32){
        float a0 = red[tid] + red[tid+32] + red[tid+64] + red[tid+96];
        #pragma unroll
        for (int o = 16; o; o >>= 1) a0 += __shfl_xor_sync(0xffffffffu, a0, o);
        if (tid == 0) g_vn[b] = sqrtf(a0);
    }

    int h = tid;
    float u = 0.f;
    for (int k0 = 0; k0 < N_; k0 += 16){
        float wb[16];
        #pragma unroll
        for (int j = 0; j < 16; j++) wb[j] = W1[(k0+j)*H_ + h];
        #pragma unroll
        for (int j = 0; j < 16; j++) u += xs[k0+j]*wb[j];
    }
    float th = tanhf(u + b1[h]);
    float s = 1.f - th*th;
    g_s[b*H_ + h] = s;
    g_c[b*H_ + h] = -2.f*th*s;
}

// ========== stage 2: z==0 -> vector part 2 (uses P);  z>=1 -> split-K A2 GEMM ==========
__global__ void __launch_bounds__(256) k_A2(
        const float* __restrict__ W1, const float* __restrict__ W2,
        const float* __restrict__ state){
    int tid = threadIdx.x;
    if (blockIdx.z == 0){
        // ---- vector part 2: w,y -> z,q2 via P -> pv,cwz -> A,C ----
        int b = blockIdx.y*4 + blockIdx.x;
        __shared__ float vs[N_];
        __shared__ float swv[H_], cwy[H_], pvs[H_], cwz[H_];
        __shared__ float Ap[2][N_], Cp[2][N_];

        if (tid < N_) vs[tid] = state[(B_+b)*N_ + tid];
        __syncthreads();

        int h = tid;
        float s = g_s[b*H_ + h];
        float c = g_c[b*H_ + h];
        float w = 0.f, y = 0.f;
        {
            const float* w2r = W2 + h*N_;
            for (int k0 = 0; k0 < N_; k0 += 16){
                float tb[16], wb[16];
                LOAD16_ROW(tb, (w2r + k0))
                #pragma unroll
                for (int j = 0; j < 16; j++) wb[j] = W1[(k0+j)*H_ + h];
                #pragma unroll
                for (int j = 0; j < 16; j++){
                    w += vs[k0+j]*tb[j];
                    y += vs[k0+j]*wb[j];
                }
            }
        }
        swv[h] = s*w;
        cwy[h] = c*w*y;
        __syncthreads();

        // z = P(s.w), q2 = P(c.w.y): coalesced P columns (P symmetric)
        float z = 0.f, q2 = 0.f;
        for (int a0 = 0; a0 < H_; a0 += 16){
            float pb[16];
            #pragma unroll
            for (int j = 0; j < 16; j++) pb[j] = g_P[(a0+j)*H_ + h];
            #pragma unroll
            for (int j = 0; j < 16; j++){
                z  += pb[j]*swv[a0+j];
                q2 += pb[j]*cwy[a0+j];
            }
        }
        pvs[h] = c*y*z + s*q2;
        cwz[h] = c*w*z;
        __syncthreads();

        // A = W2^T pv (coalesced cols), C = W1 cwz (row reads)
        {
            int i = tid & 127, hf = tid >> 7;
            const float* w1r = W1 + i*H_ + hf*128;
            float A = 0.f, Cc = 0.f;
            for (int j0 = 0; j0 < 128; j0 += 16){
                float wa[16], wc[16];
                #pragma unroll
                for (int j = 0; j < 16; j++) wa[j] = W2[(hf*128 + j0 + j)*N_ + i];
                LOAD16_ROW(wc, (w1r + j0))
                #pragma unroll
                for (int j = 0; j < 16; j++){
                    A  += wa[j]*pvs[hf*128 + j0 + j];
                    Cc += wc[j]*cwz[hf*128 + j0 + j];
                }
            }
            Ap[hf][i] = A;
            Cp[hf][i] = Cc;
        }
        __syncthreads();
        if (tid < N_){
            g_Avec[b*N_ + tid] = Ap[0][tid] + Ap[1][tid];
            g_Cvec[b*N_ + tid] = 2.f*(Cp[0][tid] + Cp[1][tid]);
        }
        return;
    }

    // ---- split-K A2 GEMM ----
    int zz = blockIdx.z - 1;
    int b = zz >> 1, ka = zz & 1;
    int g0 = blockIdx.y*64, h0 = blockIdx.x*64;
    int ty = tid >> 4, tx = tid & 15;
    __shared__ float Ps[2][16][68];
    __shared__ float Qs[2][16][68];
    __shared__ float ssm[H_];
    ssm[tid] = g_s[b*H_ + tid];
    unsigned long long accp[4][2] = {{0ull,0ull},{0ull,0ull},{0ull,0ull},{0ull,0ull}};

    int a = tid >> 4, q4 = (tid & 15)*4;
    int abase = ka*128;
    float4 pv = *(const float4*)&g_P[(abase + a)*H_ + g0 + q4];
    float4 qv = *(const float4*)&g_Q[(abase + a)*H_ + h0 + q4];
    __syncthreads();
    {
        float sa = ssm[abase + a];
        *(float4*)&Ps[0][a][q4] = pv;
        qv.x *= sa; qv.y *= sa; qv.z *= sa; qv.w *= sa;
        *(float4*)&Qs[0][a][q4] = qv;
    }
    __syncthreads();

    for (int t = 0; t < 8; t++){
        int cur = t & 1;
        if (t < 7){
            pv = *(const float4*)&g_P[(abase + (t+1)*16 + a)*H_ + g0 + q4];
            qv = *(const float4*)&g_Q[(abase + (t+1)*16 + a)*H_ + h0 + q4];
        }
        #pragma unroll
        for (int k = 0; k < 16; k++) MICRO_STEP_F32X2(Ps[cur], Qs[cur])
        if (t < 7){
            float sa = ssm[abase + (t+1)*16 + a];
            *(float4*)&Ps[cur^1][a][q4] = pv;
            qv.x *= sa; qv.y *= sa; qv.z *= sa; qv.w *= sa;
            *(float4*)&Qs[cur^1][a][q4] = qv;
        }
        __syncthreads();
    }
    UNPACK_ACC()
    float* dst = g_A2 + (ka*B_ + b)*H_*H_;
    #pragma unroll
    for (int i = 0; i < 4; i++){
        float4 o = make_float4(acc[i][0], acc[i][1], acc[i][2], acc[i][3]);
        *(float4*)&dst[(g0+ty*4+i)*H_ + h0 + tx*4] = o;
    }
}

// ========== stage 3: M = P diag(s) A2^T, upper tiles x split-K2, A2 = lo+hi ==========
__global__ void __launch_bounds__(256) k_nrm(const float* __restrict__ state,
                                             float* __restrict__ out){
    const int gt_t[10] = {0,0,0,0,1,1,1,2,2,3};
    const int ht_t[10] = {0,1,2,3,1,2,3,2,3,3};
    int b  = blockIdx.z;
    int ti = blockIdx.x;
    int ka = blockIdx.y;
    int g0 = gt_t[ti]*64, h0 = ht_t[ti]*64;
    int abase = ka*128;
    bool diag = (g0 == h0);
    int tid = threadIdx.x;
    int ty = tid >> 4, tx = tid & 15;
    __shared__ float As[2][16][68];
    __shared__ float Bs[2][16][68];
    __shared__ float Ts[64][65];
    __shared__ float ssm[H_];
    ssm[tid] = g_s[b*H_ + tid];
    unsigned long long accp[4][2] = {{0ull,0ull},{0ull,0ull},{0ull,0ull},{0ull,0ull}};

    const float* A2lo = g_A2 + b*H_*H_;
    const float* A2hi = g_A2 + (B_ + b)*H_*H_;
    int a  = tid >> 4, q4 = (tid & 15)*4;
    int rw = tid >> 2, kq = (tid & 3)*4;

    if (ka == 0){
        #pragma unroll
        for (int p = 0; p < 4; p++){
            int f = tid + p*256;
            int row = f >> 4, c4 = (f & 15)*4;
            float4 tl = *(const float4*)&A2lo[(h0+row)*H_ + g0 + c4];
            float4 thv = *(const float4*)&A2hi[(h0+row)*H_ + g0 + c4];
            Ts[row][c4+0] = tl.x+thv.x; Ts[row][c4+1] = tl.y+thv.y;
            Ts[row][c4+2] = tl.z+thv.z; Ts[row][c4+3] = tl.w+thv.w;
        }
    }

    float4 pv = *(const float4*)&g_P[(abase + a)*H_ + g0 + q4];
    float4 bl = *(const float4*)&A2lo[(h0+rw)*H_ + abase + kq];
    float4 bh = *(const float4*)&A2hi[(h0+rw)*H_ + abase + kq];
    __syncthreads();
    {
        float sa = ssm[abase + a];
        pv.x *= sa; pv.y *= sa; pv.z *= sa; pv.w *= sa;
        *(float4*)&As[0][a][q4] = pv;
        Bs[0][kq+0][rw] = bl.x+bh.x; Bs[0][kq+1][rw] = bl.y+bh.y;
        Bs[0][kq+2][rw] = bl.z+bh.z; Bs[0][kq+3][rw] = bl.w+bh.w;
    }
    __syncthreads();

    for (int t = 0; t < 8; t++){
        int cur = t & 1;
        if (t < 7){
            pv = *(const float4*)&g_P[(abase + (t+1)*16 + a)*H_ + g0 + q4];
            bl = *(const float4*)&A2lo[(h0+rw)*H_ + abase + (t+1)*16 + kq];
            bh = *(const float4*)&A2hi[(h0+rw)*H_ + abase + (t+1)*16 + kq];
        }
        #pragma unroll
        for (int k = 0; k < 16; k++) MICRO_STEP_F32X2(As[cur], Bs[cur])
        if (t < 7){
            float sa = ssm[abase + (t+1)*16 + a];
            pv.x *= sa; pv.y *= sa; pv.z *= sa; pv.w *= sa;
            *(float4*)&As[cur^1][a][q4] = pv;
            Bs[cur^1][kq+0][rw] = bl.x+bh.x; Bs[cur^1][kq+1][rw] = bl.y+bh.y;
            Bs[cur^1][kq+2][rw] = bl.z+bh.z; Bs[cur^1][kq+3][rw] = bl.w+bh.w;
        }
        __syncthreads();
    }
    UNPACK_ACC()

    const float* cb = g_c + b*H_;
    float local = 0.f;
    #pragma unroll
    for (int i = 0; i < 4; i++){
        int g = g0 + ty*4 + i;
        float cg = cb[g];
        float4 P4  = *(const float4*)&g_P[g*H_ + h0 + tx*4];
        float4 Q4  = *(const float4*)&g_Q[g*H_ + h0 + tx*4];
        float pr[4] = {P4.x, P4.y, P4.z, P4.w};
        float qr[4] = {Q4.x, Q4.y, Q4.z, Q4.w};
        if (ka == 0){
            float4 Al = *(const float4*)&A2lo[g*H_ + h0 + tx*4];
            float4 Ah = *(const float4*)&A2hi[g*H_ + h0 + tx*4];
            float ar[4] = {Al.x+Ah.x, Al.y+Ah.y, Al.z+Ah.z, Al.w+Ah.w};
            #pragma unroll
            for (int j = 0; j < 4; j++){
                int hcol = h0 + tx*4 + j;
                float wgt = diag ? ((hcol > g) ? 2.f : ((hcol == g) ? 1.f : 0.f)) : 2.f;
                float a2t = Ts[tx*4+j][ty*4+i];
                local += wgt*cg*cb[hcol]*pr[j]*(qr[j]*acc[i][j] + ar[j]*a2t);
            }
        } else {
            #pragma unroll
            for (int j = 0; j < 4; j++){
                int hcol = h0 + tx*4 + j;
                float wgt = diag ? ((hcol > g) ? 2.f : ((hcol == g) ? 1.f : 0.f)) : 2.f;
                local += wgt*cg*cb[hcol]*pr[j]*qr[j]*acc[i][j];
            }
        }
    }
    __shared__ float red[256];
    red[tid] = local;
    __syncthreads();
    for (int st = 128; st > 0; st >>= 1){
        if (tid < st) red[tid] += red[tid + st];
        __syncthreads();
    }
    __shared__ unsigned int is_last;
    if (tid == 0){
        g_part[b*20 + ti*2 + ka] = red[0];
        __threadfence();
        is_last = (atomicAdd(&g_cnt[b], 1u) == 19u);
    }
    __syncthreads();

    if (is_last && tid < N_){
        float sum = 0.f;
        #pragma unroll
        for (int i = 0; i < 20; i++) sum += g_part[b*20 + i];
        float nrm = sqrtf(fmaxf(2.f*sum, 0.f));
        float vn  = g_vn[b];
        float v   = state[(B_+b)*N_ + tid];
        float dev = state[b*N_ + tid];
        float aout = -(g_Avec[b*N_ + tid] - 0.5f*g_Cvec[b*N_ + tid])
                     / ((nrm + 1e-6f) * (vn + 1e-6f));
        out[b*N_ + tid]       = v;
        out[(B_+b)*N_ + tid]  = aout - 0.1f*dev;
    }
}

// -------- launch --------
extern "C" void kernel_launch(void* const* d_in, const int* in_sizes, int n_in,
                              void* d_out, int out_size){
    const float* t     = (const float*)d_in[0];
    const float* state = (const float*)d_in[1];
    const float* x0    = (const float*)d_in[2];
    const float* x1    = (const float*)d_in[3];
    const float* W1    = (const float*)d_in[4];
    const float* b1    = (const float*)d_in[5];
    const float* W2    = (const float*)d_in[6];
    float* out = (float*)d_out;

    k_stage1<<<48,                 256>>>(W1, W2, t, state, x0, x1, b1);
    k_A2    <<<dim3(4,4,2*B_+1),   256>>>(W1, W2, state);
    k_nrm   <<<dim3(10,2,B_),      256>>>(state, out);
}